// round 1
// baseline (speedup 1.0000x reference)
#include <cuda_runtime.h>
#include <math.h>

#define NN 100000
#define EE 1280000
#define DIN 64
#define DOUT 64
#define DEDGE 16
#define NEG 0.01f

#define SCAN_T 512
#define SCAN_BLOCKS ((NN + SCAN_T - 1) / SCAN_T)   // 196

// ---------------- device scratch (static, no allocation) ----------------
__device__ float g_xt[NN * DOUT];      // x @ W2^T
__device__ float g_sf[NN * DOUT];      // x @ W1a^T
__device__ float g_rdot[NN];           // sum leaky(x)*attn[64:]
__device__ float g_logits[EE];
__device__ int   g_count[NN];
__device__ int   g_rowptr[NN + 1];
__device__ int   g_wptr[NN];
__device__ int   g_eid[EE];
__device__ int   g_bsum[SCAN_BLOCKS];

__device__ __forceinline__ float leaky(float v) {
    return v > 0.0f ? v : NEG * v;
}

__device__ __forceinline__ float warp_sum(float v) {
    #pragma unroll
    for (int o = 16; o > 0; o >>= 1) v += __shfl_xor_sync(0xFFFFFFFFu, v, o);
    return v;
}
__device__ __forceinline__ float warp_max(float v) {
    #pragma unroll
    for (int o = 16; o > 0; o >>= 1) v = fmaxf(v, __shfl_xor_sync(0xFFFFFFFFu, v, o));
    return v;
}

// ---------------- K0: zero histogram ----------------
__global__ void k_zero_counts() {
    int i = blockIdx.x * blockDim.x + threadIdx.x;
    if (i < NN) g_count[i] = 0;
}

// ---------------- K1: node precompute ----------------
// Per node n:  g_xt[n,:] = x[n,:] @ W2^T
//              g_sf[n,:] = x[n,:] @ W1a^T   (W1a = W1[:, :64])
//              g_rdot[n] = sum_k leaky(x[n,k]) * attn[64+k]
// Weights staged in shared, k-major: sW[k*64 + d] so lanes (d) are conflict-free.
__global__ __launch_bounds__(256) void k_node(const float* __restrict__ x,
                                              const float* __restrict__ W1,
                                              const float* __restrict__ W2,
                                              const float* __restrict__ attn) {
    __shared__ float sW1a[DIN * DOUT];   // [k][d]
    __shared__ float sW2[DIN * DOUT];    // [k][d]
    __shared__ float sAttnR[DIN];
    __shared__ float sx[8][DIN];

    for (int idx = threadIdx.x; idx < DIN * DOUT; idx += blockDim.x) {
        int k = idx >> 6, d = idx & 63;
        sW1a[idx] = W1[d * (DIN + DEDGE) + k];
        sW2[idx]  = W2[d * DIN + k];
    }
    for (int idx = threadIdx.x; idx < DIN; idx += blockDim.x)
        sAttnR[idx] = attn[DOUT + idx];
    __syncthreads();

    const int lane = threadIdx.x & 31;
    const int w    = threadIdx.x >> 5;
    const int gw   = (blockIdx.x * blockDim.x + threadIdx.x) >> 5;
    const int nw   = (gridDim.x * blockDim.x) >> 5;

    for (int n = gw; n < NN; n += nw) {
        float x0 = x[n * DIN + lane];
        float x1 = x[n * DIN + lane + 32];
        sx[w][lane]      = x0;
        sx[w][lane + 32] = x1;
        __syncwarp();

        // rdot partial
        float rd = leaky(x0) * sAttnR[lane] + leaky(x1) * sAttnR[lane + 32];
        rd = warp_sum(rd);

        float a0 = 0.f, a1 = 0.f, b0 = 0.f, b1 = 0.f;
        #pragma unroll 16
        for (int k = 0; k < DIN; k++) {
            float xv = sx[w][k];
            a0 = fmaf(xv, sW1a[k * 64 + lane],      a0);
            a1 = fmaf(xv, sW1a[k * 64 + lane + 32], a1);
            b0 = fmaf(xv, sW2[k * 64 + lane],       b0);
            b1 = fmaf(xv, sW2[k * 64 + lane + 32],  b1);
        }
        g_sf[n * DOUT + lane]      = a0;
        g_sf[n * DOUT + lane + 32] = a1;
        g_xt[n * DOUT + lane]      = b0;
        g_xt[n * DOUT + lane + 32] = b1;
        if (lane == 0) g_rdot[n] = rd;
        __syncwarp();
    }
}

// ---------------- K2: per-edge logits + dst histogram ----------------
// logit_e = sum_d leaky(sf[src,d] + (edge_attr[e] @ W1b^T)[d]) * attn[d]  + rdot[dst]
__global__ __launch_bounds__(256) void k_logits(const float* __restrict__ edge_attr,
                                                const int* __restrict__ src,
                                                const int* __restrict__ dst,
                                                const float* __restrict__ W1,
                                                const float* __restrict__ attn) {
    __shared__ float sW1b[DEDGE * DOUT];   // [k][d]
    __shared__ float sAttnF[DOUT];

    for (int idx = threadIdx.x; idx < DEDGE * DOUT; idx += blockDim.x) {
        int k = idx >> 6, d = idx & 63;
        sW1b[idx] = W1[d * (DIN + DEDGE) + DIN + k];
    }
    for (int idx = threadIdx.x; idx < DOUT; idx += blockDim.x)
        sAttnF[idx] = attn[idx];
    __syncthreads();

    const int lane = threadIdx.x & 31;
    const int gw   = (blockIdx.x * blockDim.x + threadIdx.x) >> 5;
    const int nw   = (gridDim.x * blockDim.x) >> 5;

    for (int e = gw; e < EE; e += nw) {
        int s = src[e];          // broadcast
        int d = dst[e];          // broadcast
        float eav = (lane < DEDGE) ? edge_attr[e * DEDGE + lane] : 0.0f;

        float f0 = g_sf[s * DOUT + lane];
        float f1 = g_sf[s * DOUT + lane + 32];
        #pragma unroll
        for (int k = 0; k < DEDGE; k++) {
            float ek = __shfl_sync(0xFFFFFFFFu, eav, k);
            f0 = fmaf(ek, sW1b[k * 64 + lane],      f0);
            f1 = fmaf(ek, sW1b[k * 64 + lane + 32], f1);
        }
        float part = leaky(f0) * sAttnF[lane] + leaky(f1) * sAttnF[lane + 32];
        part = warp_sum(part);
        if (lane == 0) {
            g_logits[e] = part + g_rdot[d];
            atomicAdd(&g_count[d], 1);
        }
    }
}

// ---------------- K3: scan counts -> rowptr ----------------
__global__ __launch_bounds__(SCAN_T) void k_scan1() {
    __shared__ int sh[SCAN_T];
    int i = blockIdx.x * SCAN_T + threadIdx.x;
    int v = (i < NN) ? g_count[i] : 0;
    sh[threadIdx.x] = v;
    __syncthreads();
    #pragma unroll
    for (int off = 1; off < SCAN_T; off <<= 1) {
        int t = (threadIdx.x >= off) ? sh[threadIdx.x - off] : 0;
        __syncthreads();
        sh[threadIdx.x] += t;
        __syncthreads();
    }
    if (i < NN) g_rowptr[i] = sh[threadIdx.x] - v;   // exclusive
    if (threadIdx.x == SCAN_T - 1) g_bsum[blockIdx.x] = sh[SCAN_T - 1];
}

__global__ void k_scan2() {
    if (threadIdx.x == 0 && blockIdx.x == 0) {
        int run = 0;
        for (int b = 0; b < SCAN_BLOCKS; b++) {
            int t = g_bsum[b];
            g_bsum[b] = run;
            run += t;
        }
    }
}

__global__ void k_scan3() {
    int i = blockIdx.x * blockDim.x + threadIdx.x;
    if (i < NN) {
        int r = g_rowptr[i] + g_bsum[i / SCAN_T];
        g_rowptr[i] = r;
        g_wptr[i]   = r;
    }
    if (i == 0) g_rowptr[NN] = EE;
}

// ---------------- K4: scatter edge ids into CSR ----------------
__global__ void k_scatter(const int* __restrict__ dst) {
    int e = blockIdx.x * blockDim.x + threadIdx.x;
    if (e < EE) {
        int d = dst[e];
        int pos = atomicAdd(&g_wptr[d], 1);
        g_eid[pos] = e;
    }
}

// ---------------- K5: warp-per-dst softmax + aggregation ----------------
__global__ __launch_bounds__(256) void k_aggregate(const int* __restrict__ src,
                                                   const float* __restrict__ bias,
                                                   float* __restrict__ out) {
    const int lane = threadIdx.x & 31;
    const int gw   = (blockIdx.x * blockDim.x + threadIdx.x) >> 5;
    if (gw >= NN) return;
    const int n = gw;

    int beg = g_rowptr[n];
    int end = g_rowptr[n + 1];

    float b0 = bias[2 * lane];
    float b1 = bias[2 * lane + 1];

    if (beg == end) {
        out[n * DOUT + 2 * lane]     = b0;
        out[n * DOUT + 2 * lane + 1] = b1;
        return;
    }

    // pass 1: max
    float m = -INFINITY;
    for (int j = beg + lane; j < end; j += 32)
        m = fmaxf(m, g_logits[g_eid[j]]);
    m = warp_max(m);

    // pass 2: sum of exp
    float ssum = 0.0f;
    for (int j = beg + lane; j < end; j += 32)
        ssum += __expf(g_logits[g_eid[j]] - m);
    ssum = warp_sum(ssum);
    float inv = 1.0f / ssum;

    // pass 3: weighted accumulate
    float acc0 = 0.0f, acc1 = 0.0f;
    for (int j = beg; j < end; j++) {
        int e = g_eid[j];                                  // broadcast
        int s = src[e];                                    // broadcast
        float a = __expf(g_logits[e] - m) * inv;           // broadcast data
        float2 v = *reinterpret_cast<const float2*>(&g_xt[s * DOUT + 2 * lane]);
        acc0 = fmaf(a, v.x, acc0);
        acc1 = fmaf(a, v.y, acc1);
    }
    out[n * DOUT + 2 * lane]     = acc0 + b0;
    out[n * DOUT + 2 * lane + 1] = acc1 + b1;
}

// ---------------- launch ----------------
extern "C" void kernel_launch(void* const* d_in, const int* in_sizes, int n_in,
                              void* d_out, int out_size) {
    const float* x         = (const float*)d_in[0];
    const float* edge_attr = (const float*)d_in[1];
    const int*   src       = (const int*)d_in[2];
    const int*   dst       = (const int*)d_in[3];
    const float* W1        = (const float*)d_in[4];
    const float* W2        = (const float*)d_in[5];
    const float* attn      = (const float*)d_in[6];
    const float* bias      = (const float*)d_in[7];
    float* out             = (float*)d_out;

    k_zero_counts<<<(NN + 255) / 256, 256>>>();
    k_node<<<1024, 256>>>(x, W1, W2, attn);
    k_logits<<<2048, 256>>>(edge_attr, src, dst, W1, attn);
    k_scan1<<<SCAN_BLOCKS, SCAN_T>>>();
    k_scan2<<<1, 32>>>();
    k_scan3<<<(NN + 255) / 256, 256>>>();
    k_scatter<<<(EE + 255) / 256, 256>>>(dst);
    k_aggregate<<<(NN * 32 + 255) / 256, 256>>>(src, bias, out);
}

// round 2
// speedup vs baseline: 1.0168x; 1.0168x over previous
#include <cuda_runtime.h>
#include <math.h>

#define NN 100000
#define EE 1280000
#define DIN 64
#define DOUT 64
#define DEDGE 16
#define NEG 0.01f

#define SCAN_T 512
#define SCAN_BLOCKS ((NN + SCAN_T - 1) / SCAN_T)   // 196

// ---------------- device scratch (static, no allocation) ----------------
__device__ float  g_xt[NN * DOUT];      // x @ W2^T
__device__ float  g_sf[NN * DOUT];      // x @ W1a^T
__device__ float  g_rdot[NN];           // sum leaky(x)*attn[64:]
__device__ float2 g_ls[EE];             // CSR-ordered {logit, src-as-bits}
__device__ int    g_count[NN];
__device__ int    g_rowptr[NN + 1];
__device__ int    g_wptr[NN];
__device__ int    g_bsum[SCAN_BLOCKS];

__device__ __forceinline__ float leaky(float v) {
    return v > 0.0f ? v : NEG * v;
}
__device__ __forceinline__ float warp_sum(float v) {
    #pragma unroll
    for (int o = 16; o > 0; o >>= 1) v += __shfl_xor_sync(0xFFFFFFFFu, v, o);
    return v;
}
__device__ __forceinline__ float warp_max(float v) {
    #pragma unroll
    for (int o = 16; o > 0; o >>= 1) v = fmaxf(v, __shfl_xor_sync(0xFFFFFFFFu, v, o));
    return v;
}

// ---------------- K0: zero histogram ----------------
__global__ void k_zero_counts() {
    int i = blockIdx.x * blockDim.x + threadIdx.x;
    if (i < NN) g_count[i] = 0;
}

// ---------------- Kh: dst histogram ----------------
__global__ __launch_bounds__(256) void k_hist(const int* __restrict__ dst) {
    int e = blockIdx.x * blockDim.x + threadIdx.x;
    if (e < EE) atomicAdd(&g_count[dst[e]], 1);
}

// ---------------- K1: node precompute ----------------
__global__ __launch_bounds__(256) void k_node(const float* __restrict__ x,
                                              const float* __restrict__ W1,
                                              const float* __restrict__ W2,
                                              const float* __restrict__ attn) {
    __shared__ float sW1a[DIN * DOUT];   // [k][d]
    __shared__ float sW2[DIN * DOUT];    // [k][d]
    __shared__ float sAttnR[DIN];
    __shared__ float sx[8][DIN];

    for (int idx = threadIdx.x; idx < DIN * DOUT; idx += blockDim.x) {
        int k = idx >> 6, d = idx & 63;
        sW1a[idx] = W1[d * (DIN + DEDGE) + k];
        sW2[idx]  = W2[d * DIN + k];
    }
    for (int idx = threadIdx.x; idx < DIN; idx += blockDim.x)
        sAttnR[idx] = attn[DOUT + idx];
    __syncthreads();

    const int lane = threadIdx.x & 31;
    const int w    = threadIdx.x >> 5;
    const int gw   = (blockIdx.x * blockDim.x + threadIdx.x) >> 5;
    const int nw   = (gridDim.x * blockDim.x) >> 5;

    for (int n = gw; n < NN; n += nw) {
        float x0 = x[n * DIN + lane];
        float x1 = x[n * DIN + lane + 32];
        sx[w][lane]      = x0;
        sx[w][lane + 32] = x1;
        __syncwarp();

        float rd = leaky(x0) * sAttnR[lane] + leaky(x1) * sAttnR[lane + 32];
        rd = warp_sum(rd);

        float a0 = 0.f, a1 = 0.f, b0 = 0.f, b1 = 0.f;
        #pragma unroll 16
        for (int k = 0; k < DIN; k++) {
            float xv = sx[w][k];
            a0 = fmaf(xv, sW1a[k * 64 + lane],      a0);
            a1 = fmaf(xv, sW1a[k * 64 + lane + 32], a1);
            b0 = fmaf(xv, sW2[k * 64 + lane],       b0);
            b1 = fmaf(xv, sW2[k * 64 + lane + 32],  b1);
        }
        g_sf[n * DOUT + lane]      = a0;
        g_sf[n * DOUT + lane + 32] = a1;
        g_xt[n * DOUT + lane]      = b0;
        g_xt[n * DOUT + lane + 32] = b1;
        if (lane == 0) g_rdot[n] = rd;
        __syncwarp();
    }
}

// ---------------- scan counts -> rowptr ----------------
__global__ __launch_bounds__(SCAN_T) void k_scan1() {
    __shared__ int sh[SCAN_T];
    int i = blockIdx.x * SCAN_T + threadIdx.x;
    int v = (i < NN) ? g_count[i] : 0;
    sh[threadIdx.x] = v;
    __syncthreads();
    #pragma unroll
    for (int off = 1; off < SCAN_T; off <<= 1) {
        int t = (threadIdx.x >= off) ? sh[threadIdx.x - off] : 0;
        __syncthreads();
        sh[threadIdx.x] += t;
        __syncthreads();
    }
    if (i < NN) g_rowptr[i] = sh[threadIdx.x] - v;   // exclusive
    if (threadIdx.x == SCAN_T - 1) g_bsum[blockIdx.x] = sh[SCAN_T - 1];
}

__global__ void k_scan2() {
    if (threadIdx.x == 0 && blockIdx.x == 0) {
        int run = 0;
        for (int b = 0; b < SCAN_BLOCKS; b++) {
            int t = g_bsum[b];
            g_bsum[b] = run;
            run += t;
        }
    }
}

__global__ void k_scan3() {
    int i = blockIdx.x * blockDim.x + threadIdx.x;
    if (i < NN) {
        int r = g_rowptr[i] + g_bsum[i / SCAN_T];
        g_rowptr[i] = r;
        g_wptr[i]   = r;
    }
    if (i == 0) g_rowptr[NN] = EE;
}

// ---------------- K2: per-edge logits, scattered directly into CSR ----------------
__global__ __launch_bounds__(256) void k_logits(const float* __restrict__ edge_attr,
                                                const int* __restrict__ src,
                                                const int* __restrict__ dst,
                                                const float* __restrict__ W1,
                                                const float* __restrict__ attn) {
    __shared__ float sW1b[DEDGE * DOUT];   // [k][d]
    __shared__ float sAttnF[DOUT];

    for (int idx = threadIdx.x; idx < DEDGE * DOUT; idx += blockDim.x) {
        int k = idx >> 6, d = idx & 63;
        sW1b[idx] = W1[d * (DIN + DEDGE) + DIN + k];
    }
    for (int idx = threadIdx.x; idx < DOUT; idx += blockDim.x)
        sAttnF[idx] = attn[idx];
    __syncthreads();

    const int lane = threadIdx.x & 31;
    const int gw   = (blockIdx.x * blockDim.x + threadIdx.x) >> 5;
    const int nw   = (gridDim.x * blockDim.x) >> 5;

    for (int e = gw; e < EE; e += nw) {
        int s = src[e];          // broadcast
        int d = dst[e];          // broadcast
        float eav = (lane < DEDGE) ? edge_attr[e * DEDGE + lane] : 0.0f;

        float f0 = g_sf[s * DOUT + lane];
        float f1 = g_sf[s * DOUT + lane + 32];
        #pragma unroll
        for (int k = 0; k < DEDGE; k++) {
            float ek = __shfl_sync(0xFFFFFFFFu, eav, k);
            f0 = fmaf(ek, sW1b[k * 64 + lane],      f0);
            f1 = fmaf(ek, sW1b[k * 64 + lane + 32], f1);
        }
        float part = leaky(f0) * sAttnF[lane] + leaky(f1) * sAttnF[lane + 32];
        part = warp_sum(part);
        if (lane == 0) {
            int pos = atomicAdd(&g_wptr[d], 1);
            g_ls[pos] = make_float2(part + g_rdot[d], __int_as_float(s));
        }
    }
}

// ---------------- K5: warp-per-dst softmax + aggregation ----------------
__global__ __launch_bounds__(256) void k_aggregate(const float* __restrict__ bias,
                                                   float* __restrict__ out) {
    const int lane = threadIdx.x & 31;
    const int gw   = (blockIdx.x * blockDim.x + threadIdx.x) >> 5;
    if (gw >= NN) return;
    const int n = gw;

    int beg = g_rowptr[n];
    int end = g_rowptr[n + 1];
    int cnt = end - beg;

    float b0 = bias[2 * lane];
    float b1 = bias[2 * lane + 1];

    if (cnt == 0) {
        out[n * DOUT + 2 * lane]     = b0;
        out[n * DOUT + 2 * lane + 1] = b1;
        return;
    }

    // Stage first 32 entries in registers (one coalesced float2 load covers
    // the whole segment for the vast majority of nodes; avg degree 12.8).
    float2 v = make_float2(-INFINITY, 0.0f);
    if (lane < cnt) v = g_ls[beg + lane];

    // max
    float lm = v.x;
    for (int j = beg + 32 + lane; j < end; j += 32)
        lm = fmaxf(lm, g_ls[j].x);
    float m = warp_max(lm);

    // sum of exp
    float le = (lane < cnt) ? __expf(v.x - m) : 0.0f;
    for (int j = beg + 32 + lane; j < end; j += 32)
        le += __expf(g_ls[j].x - m);
    float inv = 1.0f / warp_sum(le);

    // weighted accumulate (register-staged head via shfl, tail via uniform loads)
    float acc0 = 0.0f, acc1 = 0.0f;
    int lim = cnt < 32 ? cnt : 32;
    #pragma unroll 4
    for (int idx = 0; idx < lim; idx++) {
        float l = __shfl_sync(0xFFFFFFFFu, v.x, idx);
        int   s = __float_as_int(__shfl_sync(0xFFFFFFFFu, v.y, idx));
        float a = __expf(l - m) * inv;
        float2 xv = *reinterpret_cast<const float2*>(&g_xt[s * DOUT + 2 * lane]);
        acc0 = fmaf(a, xv.x, acc0);
        acc1 = fmaf(a, xv.y, acc1);
    }
    for (int j = beg + 32; j < end; j++) {
        float2 lsv = g_ls[j];                       // lane-uniform broadcast load
        int   s = __float_as_int(lsv.y);
        float a = __expf(lsv.x - m) * inv;
        float2 xv = *reinterpret_cast<const float2*>(&g_xt[s * DOUT + 2 * lane]);
        acc0 = fmaf(a, xv.x, acc0);
        acc1 = fmaf(a, xv.y, acc1);
    }
    out[n * DOUT + 2 * lane]     = acc0 + b0;
    out[n * DOUT + 2 * lane + 1] = acc1 + b1;
}

// ---------------- launch ----------------
extern "C" void kernel_launch(void* const* d_in, const int* in_sizes, int n_in,
                              void* d_out, int out_size) {
    const float* x         = (const float*)d_in[0];
    const float* edge_attr = (const float*)d_in[1];
    const int*   src       = (const int*)d_in[2];
    const int*   dst       = (const int*)d_in[3];
    const float* W1        = (const float*)d_in[4];
    const float* W2        = (const float*)d_in[5];
    const float* attn      = (const float*)d_in[6];
    const float* bias      = (const float*)d_in[7];
    float* out             = (float*)d_out;

    k_zero_counts<<<(NN + 255) / 256, 256>>>();
    k_hist<<<(EE + 255) / 256, 256>>>(dst);
    k_node<<<1024, 256>>>(x, W1, W2, attn);
    k_scan1<<<SCAN_BLOCKS, SCAN_T>>>();
    k_scan2<<<1, 32>>>();
    k_scan3<<<(NN + 255) / 256, 256>>>();
    k_logits<<<2048, 256>>>(edge_attr, src, dst, W1, attn);
    k_aggregate<<<(NN * 32 + 255) / 256, 256>>>(bias, out);
}

// round 3
// speedup vs baseline: 1.2070x; 1.1871x over previous
#include <cuda_runtime.h>
#include <math.h>

#define NN 100000
#define EE 1280000
#define DIN 64
#define DOUT 64
#define DEDGE 16
#define NEG 0.01f

#define SCAN_T 512
#define SCAN_BLOCKS ((NN + SCAN_T - 1) / SCAN_T)   // 196

// ---------------- device scratch (static, no allocation) ----------------
__device__ float  g_xt[NN * DOUT];      // x @ W2^T, natural [n][d]
__device__ float2 g_sf2[NN * 32];       // x @ W1a^T, paired: [n][L] = (d=L, d=L+32)
__device__ float  g_rdot[NN];
__device__ float2 g_ls[EE];             // CSR-ordered {logit, src-as-bits}
__device__ int    g_count[NN];
__device__ int    g_rowptr[NN + 1];
__device__ int    g_wptr[NN];
__device__ int    g_bsum[SCAN_BLOCKS];

__device__ __forceinline__ float leaky(float v) {
    return fmaxf(v, NEG * v);
}
__device__ __forceinline__ float warp_sum(float v) {
    #pragma unroll
    for (int o = 16; o > 0; o >>= 1) v += __shfl_xor_sync(0xFFFFFFFFu, v, o);
    return v;
}
__device__ __forceinline__ float warp_max(float v) {
    #pragma unroll
    for (int o = 16; o > 0; o >>= 1) v = fmaxf(v, __shfl_xor_sync(0xFFFFFFFFu, v, o));
    return v;
}

// packed f32x2 helpers
__device__ __forceinline__ unsigned long long packf2(float lo, float hi) {
    unsigned long long r;
    asm("mov.b64 %0, {%1, %2};" : "=l"(r) : "f"(lo), "f"(hi));
    return r;
}
__device__ __forceinline__ void unpackf2(unsigned long long v, float& lo, float& hi) {
    asm("mov.b64 {%0, %1}, %2;" : "=f"(lo), "=f"(hi) : "l"(v));
}
__device__ __forceinline__ void ffma2(unsigned long long& acc,
                                      unsigned long long a,
                                      unsigned long long b) {
    asm("fma.rn.f32x2 %0, %1, %2, %0;" : "+l"(acc) : "l"(a), "l"(b));
}

// ---------------- K0: zero histogram ----------------
__global__ void k_zero_counts() {
    int i = blockIdx.x * blockDim.x + threadIdx.x;
    if (i < NN) g_count[i] = 0;
}

// ---------------- Kh: dst histogram ----------------
__global__ __launch_bounds__(256) void k_hist(const int* __restrict__ dst) {
    int e = blockIdx.x * blockDim.x + threadIdx.x;
    if (e < EE) atomicAdd(&g_count[dst[e]], 1);
}

// ---------------- K1: node precompute ----------------
__global__ __launch_bounds__(256) void k_node(const float* __restrict__ x,
                                              const float* __restrict__ W1,
                                              const float* __restrict__ W2,
                                              const float* __restrict__ attn) {
    __shared__ float sW1a[DIN * DOUT];   // [k][d]
    __shared__ float sW2[DIN * DOUT];    // [k][d]
    __shared__ float sAttnR[DIN];
    __shared__ float sx[8][DIN];

    for (int idx = threadIdx.x; idx < DIN * DOUT; idx += blockDim.x) {
        int k = idx >> 6, d = idx & 63;
        sW1a[idx] = W1[d * (DIN + DEDGE) + k];
        sW2[idx]  = W2[d * DIN + k];
    }
    for (int idx = threadIdx.x; idx < DIN; idx += blockDim.x)
        sAttnR[idx] = attn[DOUT + idx];
    __syncthreads();

    const int lane = threadIdx.x & 31;
    const int w    = threadIdx.x >> 5;
    const int gw   = (blockIdx.x * blockDim.x + threadIdx.x) >> 5;
    const int nw   = (gridDim.x * blockDim.x) >> 5;

    for (int n = gw; n < NN; n += nw) {
        float x0 = x[n * DIN + lane];
        float x1 = x[n * DIN + lane + 32];
        sx[w][lane]      = x0;
        sx[w][lane + 32] = x1;
        __syncwarp();

        float rd = leaky(x0) * sAttnR[lane] + leaky(x1) * sAttnR[lane + 32];
        rd = warp_sum(rd);

        float a0 = 0.f, a1 = 0.f, b0 = 0.f, b1 = 0.f;
        #pragma unroll 16
        for (int k = 0; k < DIN; k++) {
            float xv = sx[w][k];
            a0 = fmaf(xv, sW1a[k * 64 + lane],      a0);
            a1 = fmaf(xv, sW1a[k * 64 + lane + 32], a1);
            b0 = fmaf(xv, sW2[k * 64 + lane],       b0);
            b1 = fmaf(xv, sW2[k * 64 + lane + 32],  b1);
        }
        g_sf2[n * 32 + lane] = make_float2(a0, a1);
        g_xt[n * DOUT + lane]      = b0;
        g_xt[n * DOUT + lane + 32] = b1;
        if (lane == 0) g_rdot[n] = rd;
        __syncwarp();
    }
}

// ---------------- scan counts -> rowptr ----------------
__global__ __launch_bounds__(SCAN_T) void k_scan1() {
    __shared__ int sh[SCAN_T];
    int i = blockIdx.x * SCAN_T + threadIdx.x;
    int v = (i < NN) ? g_count[i] : 0;
    sh[threadIdx.x] = v;
    __syncthreads();
    #pragma unroll
    for (int off = 1; off < SCAN_T; off <<= 1) {
        int t = (threadIdx.x >= off) ? sh[threadIdx.x - off] : 0;
        __syncthreads();
        sh[threadIdx.x] += t;
        __syncthreads();
    }
    if (i < NN) g_rowptr[i] = sh[threadIdx.x] - v;   // exclusive
    if (threadIdx.x == SCAN_T - 1) g_bsum[blockIdx.x] = sh[SCAN_T - 1];
}

// parallel exclusive scan of the 196 block sums (single block)
__global__ __launch_bounds__(256) void k_scan2() {
    __shared__ int sh[256];
    int t = threadIdx.x;
    int v = (t < SCAN_BLOCKS) ? g_bsum[t] : 0;
    sh[t] = v;
    __syncthreads();
    #pragma unroll
    for (int off = 1; off < 256; off <<= 1) {
        int tv = (t >= off) ? sh[t - off] : 0;
        __syncthreads();
        sh[t] += tv;
        __syncthreads();
    }
    if (t < SCAN_BLOCKS) g_bsum[t] = sh[t] - v;      // exclusive
}

__global__ void k_scan3() {
    int i = blockIdx.x * blockDim.x + threadIdx.x;
    if (i < NN) {
        int r = g_rowptr[i] + g_bsum[i / SCAN_T];
        g_rowptr[i] = r;
        g_wptr[i]   = r;
    }
    if (i == 0) g_rowptr[NN] = EE;
}

// ---------------- K2: per-edge logits, scattered directly into CSR ----------------
// warp handles 32 consecutive edges; lane L owns dims (L, L+32) packed as f32x2.
__global__ __launch_bounds__(256) void k_logits(const float* __restrict__ edge_attr,
                                                const int* __restrict__ src,
                                                const int* __restrict__ dst,
                                                const float* __restrict__ W1,
                                                const float* __restrict__ attn) {
    __shared__ float2 sW[DEDGE * 32];    // [k][L] = (W1b[L][k], W1b[L+32][k])

    for (int idx = threadIdx.x; idx < DEDGE * 32; idx += blockDim.x) {
        int k = idx >> 5, L = idx & 31;
        sW[idx] = make_float2(W1[L * (DIN + DEDGE) + DIN + k],
                              W1[(L + 32) * (DIN + DEDGE) + DIN + k]);
    }
    __syncthreads();

    const int L = threadIdx.x & 31;

    // weights into registers (held across all 32 edges)
    unsigned long long wp[DEDGE];
    #pragma unroll
    for (int k = 0; k < DEDGE; k++) {
        float2 t = sW[k * 32 + L];
        wp[k] = packf2(t.x, t.y);
    }
    const float aL = __ldg(&attn[L]);
    const float aH = __ldg(&attn[L + 32]);

    const int gwarp = blockIdx.x * 8 + (threadIdx.x >> 5);
    const int base  = gwarp * 32;

    const int s_own = src[base + L];     // coalesced
    const int d_own = dst[base + L];     // coalesced
    const float4* ea4 = (const float4*)edge_attr;

    #pragma unroll 2
    for (int i = 0; i < 32; i++) {
        const int e = base + i;
        const int s = __shfl_sync(0xFFFFFFFFu, s_own, i);

        float2 sf = g_sf2[s * 32 + L];                    // single LDG.64 gather
        unsigned long long f = packf2(sf.x, sf.y);

        #pragma unroll
        for (int g = 0; g < 4; g++) {
            float4 ev = __ldg(&ea4[e * 4 + g]);           // lane-uniform broadcast
            ffma2(f, wp[4 * g + 0], packf2(ev.x, ev.x));
            ffma2(f, wp[4 * g + 1], packf2(ev.y, ev.y));
            ffma2(f, wp[4 * g + 2], packf2(ev.z, ev.z));
            ffma2(f, wp[4 * g + 3], packf2(ev.w, ev.w));
        }

        float flo, fhi;
        unpackf2(f, flo, fhi);
        float p = leaky(flo) * aL + leaky(fhi) * aH;
        p = warp_sum(p);

        const int d = __shfl_sync(0xFFFFFFFFu, d_own, i);
        if (L == 0) {
            int pos = atomicAdd(&g_wptr[d], 1);
            g_ls[pos] = make_float2(p + g_rdot[d], __int_as_float(s));
        }
    }
}

// ---------------- K5: warp-per-dst softmax + aggregation ----------------
__global__ __launch_bounds__(256) void k_aggregate(const float* __restrict__ bias,
                                                   float* __restrict__ out) {
    const int lane = threadIdx.x & 31;
    const int gw   = (blockIdx.x * blockDim.x + threadIdx.x) >> 5;
    if (gw >= NN) return;
    const int n = gw;

    int beg = g_rowptr[n];
    int end = g_rowptr[n + 1];
    int cnt = end - beg;

    float b0 = bias[2 * lane];
    float b1 = bias[2 * lane + 1];

    if (cnt == 0) {
        out[n * DOUT + 2 * lane]     = b0;
        out[n * DOUT + 2 * lane + 1] = b1;
        return;
    }

    float2 v = make_float2(-INFINITY, 0.0f);
    if (lane < cnt) v = g_ls[beg + lane];

    float lm = v.x;
    for (int j = beg + 32 + lane; j < end; j += 32)
        lm = fmaxf(lm, g_ls[j].x);
    float m = warp_max(lm);

    float le = (lane < cnt) ? __expf(v.x - m) : 0.0f;
    for (int j = beg + 32 + lane; j < end; j += 32)
        le += __expf(g_ls[j].x - m);
    float inv = 1.0f / warp_sum(le);

    float acc0 = 0.0f, acc1 = 0.0f;
    int lim = cnt < 32 ? cnt : 32;
    #pragma unroll 4
    for (int idx = 0; idx < lim; idx++) {
        float l = __shfl_sync(0xFFFFFFFFu, v.x, idx);
        int   s = __float_as_int(__shfl_sync(0xFFFFFFFFu, v.y, idx));
        float a = __expf(l - m) * inv;
        float2 xv = *reinterpret_cast<const float2*>(&g_xt[s * DOUT + 2 * lane]);
        acc0 = fmaf(a, xv.x, acc0);
        acc1 = fmaf(a, xv.y, acc1);
    }
    for (int j = beg + 32; j < end; j++) {
        float2 lsv = g_ls[j];
        int   s = __float_as_int(lsv.y);
        float a = __expf(lsv.x - m) * inv;
        float2 xv = *reinterpret_cast<const float2*>(&g_xt[s * DOUT + 2 * lane]);
        acc0 = fmaf(a, xv.x, acc0);
        acc1 = fmaf(a, xv.y, acc1);
    }
    out[n * DOUT + 2 * lane]     = acc0 + b0;
    out[n * DOUT + 2 * lane + 1] = acc1 + b1;
}

// ---------------- launch ----------------
extern "C" void kernel_launch(void* const* d_in, const int* in_sizes, int n_in,
                              void* d_out, int out_size) {
    const float* x         = (const float*)d_in[0];
    const float* edge_attr = (const float*)d_in[1];
    const int*   src       = (const int*)d_in[2];
    const int*   dst       = (const int*)d_in[3];
    const float* W1        = (const float*)d_in[4];
    const float* W2        = (const float*)d_in[5];
    const float* attn      = (const float*)d_in[6];
    const float* bias      = (const float*)d_in[7];
    float* out             = (float*)d_out;

    k_zero_counts<<<(NN + 255) / 256, 256>>>();
    k_hist<<<(EE + 255) / 256, 256>>>(dst);
    k_node<<<1024, 256>>>(x, W1, W2, attn);
    k_scan1<<<SCAN_BLOCKS, SCAN_T>>>();
    k_scan2<<<1, 256>>>();
    k_scan3<<<(NN + 255) / 256, 256>>>();
    k_logits<<<EE / 256, 256>>>(edge_attr, src, dst, W1, attn);
    k_aggregate<<<(NN * 32 + 255) / 256, 256>>>(bias, out);
}

// round 4
// speedup vs baseline: 1.3712x; 1.1360x over previous
#include <cuda_runtime.h>
#include <math.h>

#define NN 100000
#define EE 1280000
#define DIN 64
#define DOUT 64
#define DEDGE 16
#define NEG 0.01f

#define SCAN_T 512
#define SCAN_BLOCKS ((NN + SCAN_T - 1) / SCAN_T)   // 196

#define TM 128                                     // nodes per k_node block
#define NODE_BLOCKS ((NN + TM - 1) / TM)           // 782

typedef unsigned long long ull;

// ---------------- device scratch (static, no allocation) ----------------
__device__ float  g_xt[NN * DOUT];      // x @ W2^T, natural [n][d]
__device__ float  g_sf[NN * DOUT];      // x @ W1a^T, natural [n][d]
__device__ float  g_rdot[NN];
__device__ float2 g_ls[EE];             // CSR-ordered {logit, src-as-bits}
__device__ int    g_count[NN];
__device__ int    g_rowptr[NN + 1];
__device__ int    g_wptr[NN];
__device__ int    g_bsum[SCAN_BLOCKS];

__device__ __forceinline__ float leaky(float v) {
    return fmaxf(v, NEG * v);
}
__device__ __forceinline__ float warp_sum(float v) {
    #pragma unroll
    for (int o = 16; o > 0; o >>= 1) v += __shfl_xor_sync(0xFFFFFFFFu, v, o);
    return v;
}
__device__ __forceinline__ float warp_max(float v) {
    #pragma unroll
    for (int o = 16; o > 0; o >>= 1) v = fmaxf(v, __shfl_xor_sync(0xFFFFFFFFu, v, o));
    return v;
}

// packed f32x2 helpers
__device__ __forceinline__ ull packf2(float lo, float hi) {
    ull r;
    asm("mov.b64 %0, {%1, %2};" : "=l"(r) : "f"(lo), "f"(hi));
    return r;
}
__device__ __forceinline__ void unpackf2(ull v, float& lo, float& hi) {
    asm("mov.b64 {%0, %1}, %2;" : "=f"(lo), "=f"(hi) : "l"(v));
}
__device__ __forceinline__ void ffma2(ull& acc, ull a, ull b) {
    asm("fma.rn.f32x2 %0, %1, %2, %0;" : "+l"(acc) : "l"(a), "l"(b));
}

// ---------------- K0: zero histogram ----------------
__global__ void k_zero_counts() {
    int i = blockIdx.x * blockDim.x + threadIdx.x;
    if (i < NN) g_count[i] = 0;
}

// ---------------- Kh: dst histogram (4 edges/thread) ----------------
__global__ __launch_bounds__(256) void k_hist(const int* __restrict__ dst) {
    int t = blockIdx.x * blockDim.x + threadIdx.x;
    if (t * 4 < EE) {
        int4 d4 = ((const int4*)dst)[t];
        atomicAdd(&g_count[d4.x], 1);
        atomicAdd(&g_count[d4.y], 1);
        atomicAdd(&g_count[d4.z], 1);
        atomicAdd(&g_count[d4.w], 1);
    }
}

// ---------------- K1: node precompute (register-tiled GEMM) ----------------
// Block computes a [128 nodes] x [128 outputs] tile.
// Outputs d<64 -> g_sf (x@W1a^T); d>=64 -> g_xt (x@W2^T). rdot folded in.
// Thread (ty,tx): nodes ty*8..+7, outputs tx*8..+7 as 4 f32x2 pairs.
__global__ __launch_bounds__(256, 2) void k_node(const float* __restrict__ x,
                                                 const float* __restrict__ W1,
                                                 const float* __restrict__ W2,
                                                 const float* __restrict__ attn) {
    __shared__ float xS[TM][65];          // [node][k], stride 65 -> conflict-free
    __shared__ float sW[DIN][128];        // [k][d]; d<64: W1a, d>=64: W2
    __shared__ float sAttnR[DIN];

    const int tid = threadIdx.x;
    const int n0  = blockIdx.x * TM;

    for (int idx = tid; idx < DIN * 128; idx += 256) {
        int k = idx >> 7, d = idx & 127;
        sW[k][d] = (d < 64) ? W1[d * (DIN + DEDGE) + k]
                            : W2[(d - 64) * DIN + k];
    }
    if (tid < DIN) sAttnR[tid] = attn[DOUT + tid];

    for (int idx = tid; idx < TM * DIN; idx += 256) {
        int nl = idx >> 6, k = idx & 63;
        int n = n0 + nl;
        if (n >= NN) n = NN - 1;
        xS[nl][k] = x[n * DIN + k];
    }
    __syncthreads();

    const int ty = tid >> 4, tx = tid & 15;
    const int nbase = ty * 8;

    ull acc[8][4];
    #pragma unroll
    for (int j = 0; j < 8; j++)
        #pragma unroll
        for (int p = 0; p < 4; p++) acc[j][p] = 0ULL;

    #pragma unroll 4
    for (int k = 0; k < DIN; k++) {
        // 8 consecutive weights for this thread = 4 ready-made f32x2 pairs
        ulonglong2 wA = *reinterpret_cast<const ulonglong2*>(&sW[k][tx * 8]);
        ulonglong2 wB = *reinterpret_cast<const ulonglong2*>(&sW[k][tx * 8 + 4]);
        #pragma unroll
        for (int j = 0; j < 8; j++) {
            float xv = xS[nbase + j][k];
            ull xp = packf2(xv, xv);
            ffma2(acc[j][0], wA.x, xp);
            ffma2(acc[j][1], wA.y, xp);
            ffma2(acc[j][2], wB.x, xp);
            ffma2(acc[j][3], wB.y, xp);
        }
    }

    // rdot (threads 0..127, one node each, xS already resident)
    if (tid < TM) {
        int n = n0 + tid;
        if (n < NN) {
            float rd = 0.0f;
            #pragma unroll 8
            for (int k = 0; k < DIN; k++)
                rd += leaky(xS[tid][k]) * sAttnR[k];
            g_rdot[n] = rd;
        }
    }

    // stores: 8 nodes x 8 outputs, STG.128 pairs
    #pragma unroll
    for (int j = 0; j < 8; j++) {
        int n = n0 + nbase + j;
        if (n >= NN) continue;
        float* dst = (tx < 8) ? &g_sf[n * DOUT + tx * 8]
                              : &g_xt[n * DOUT + (tx - 8) * 8];
        ulonglong2 v0; v0.x = acc[j][0]; v0.y = acc[j][1];
        ulonglong2 v1; v1.x = acc[j][2]; v1.y = acc[j][3];
        *reinterpret_cast<ulonglong2*>(dst)     = v0;
        *reinterpret_cast<ulonglong2*>(dst + 4) = v1;
    }
}

// ---------------- scan counts -> rowptr ----------------
__global__ __launch_bounds__(SCAN_T) void k_scan1() {
    __shared__ int sh[SCAN_T];
    int i = blockIdx.x * SCAN_T + threadIdx.x;
    int v = (i < NN) ? g_count[i] : 0;
    sh[threadIdx.x] = v;
    __syncthreads();
    #pragma unroll
    for (int off = 1; off < SCAN_T; off <<= 1) {
        int t = (threadIdx.x >= off) ? sh[threadIdx.x - off] : 0;
        __syncthreads();
        sh[threadIdx.x] += t;
        __syncthreads();
    }
    if (i < NN) g_rowptr[i] = sh[threadIdx.x] - v;   // exclusive
    if (threadIdx.x == SCAN_T - 1) g_bsum[blockIdx.x] = sh[SCAN_T - 1];
}

__global__ __launch_bounds__(256) void k_scan2() {
    __shared__ int sh[256];
    int t = threadIdx.x;
    int v = (t < SCAN_BLOCKS) ? g_bsum[t] : 0;
    sh[t] = v;
    __syncthreads();
    #pragma unroll
    for (int off = 1; off < 256; off <<= 1) {
        int tv = (t >= off) ? sh[t - off] : 0;
        __syncthreads();
        sh[t] += tv;
        __syncthreads();
    }
    if (t < SCAN_BLOCKS) g_bsum[t] = sh[t] - v;      // exclusive
}

__global__ void k_scan3() {
    int i = blockIdx.x * blockDim.x + threadIdx.x;
    if (i < NN) {
        int r = g_rowptr[i] + g_bsum[i / SCAN_T];
        g_rowptr[i] = r;
        g_wptr[i]   = r;
    }
    if (i == 0) g_rowptr[NN] = EE;
}

// ---------------- K2: per-edge logits, scattered directly into CSR ----------------
// warp handles 32 consecutive edges; lane L owns dims (2L, 2L+1) packed f32x2.
__global__ __launch_bounds__(256) void k_logits(const float* __restrict__ edge_attr,
                                                const int* __restrict__ src,
                                                const int* __restrict__ dst,
                                                const float* __restrict__ W1,
                                                const float* __restrict__ attn) {
    __shared__ float2 sW[DEDGE * 32];    // [k][L] = (W1b[2L][k], W1b[2L+1][k])

    for (int idx = threadIdx.x; idx < DEDGE * 32; idx += blockDim.x) {
        int k = idx >> 5, L = idx & 31;
        sW[idx] = make_float2(W1[(2 * L) * (DIN + DEDGE) + DIN + k],
                              W1[(2 * L + 1) * (DIN + DEDGE) + DIN + k]);
    }
    __syncthreads();

    const int L = threadIdx.x & 31;

    ull wp[DEDGE];
    #pragma unroll
    for (int k = 0; k < DEDGE; k++) {
        float2 t = sW[k * 32 + L];
        wp[k] = packf2(t.x, t.y);
    }
    const float aL = __ldg(&attn[2 * L]);
    const float aH = __ldg(&attn[2 * L + 1]);

    const int gwarp = blockIdx.x * 8 + (threadIdx.x >> 5);
    const int base  = gwarp * 32;

    const int s_own = src[base + L];     // coalesced
    const int d_own = dst[base + L];     // coalesced
    const float4* ea4 = (const float4*)edge_attr;

    #pragma unroll 2
    for (int i = 0; i < 32; i++) {
        const int e = base + i;
        const int s = __shfl_sync(0xFFFFFFFFu, s_own, i);

        float2 sf = *reinterpret_cast<const float2*>(&g_sf[s * DOUT + 2 * L]);
        ull f = packf2(sf.x, sf.y);

        #pragma unroll
        for (int g = 0; g < 4; g++) {
            float4 ev = __ldg(&ea4[e * 4 + g]);           // lane-uniform broadcast
            ffma2(f, wp[4 * g + 0], packf2(ev.x, ev.x));
            ffma2(f, wp[4 * g + 1], packf2(ev.y, ev.y));
            ffma2(f, wp[4 * g + 2], packf2(ev.z, ev.z));
            ffma2(f, wp[4 * g + 3], packf2(ev.w, ev.w));
        }

        float flo, fhi;
        unpackf2(f, flo, fhi);
        float p = leaky(flo) * aL + leaky(fhi) * aH;
        p = warp_sum(p);

        const int d = __shfl_sync(0xFFFFFFFFu, d_own, i);
        if (L == 0) {
            int pos = atomicAdd(&g_wptr[d], 1);
            g_ls[pos] = make_float2(p + g_rdot[d], __int_as_float(s));
        }
    }
}

// ---------------- K5: warp-per-dst softmax + aggregation ----------------
__global__ __launch_bounds__(256) void k_aggregate(const float* __restrict__ bias,
                                                   float* __restrict__ out) {
    const int lane = threadIdx.x & 31;
    const int gw   = (blockIdx.x * blockDim.x + threadIdx.x) >> 5;
    if (gw >= NN) return;
    const int n = gw;

    int beg = g_rowptr[n];
    int end = g_rowptr[n + 1];
    int cnt = end - beg;

    float b0 = bias[2 * lane];
    float b1 = bias[2 * lane + 1];

    if (cnt == 0) {
        out[n * DOUT + 2 * lane]     = b0;
        out[n * DOUT + 2 * lane + 1] = b1;
        return;
    }

    float2 v = make_float2(-INFINITY, 0.0f);
    if (lane < cnt) v = g_ls[beg + lane];

    float lm = v.x;
    for (int j = beg + 32 + lane; j < end; j += 32)
        lm = fmaxf(lm, g_ls[j].x);
    float m = warp_max(lm);

    float le = (lane < cnt) ? __expf(v.x - m) : 0.0f;
    for (int j = beg + 32 + lane; j < end; j += 32)
        le += __expf(g_ls[j].x - m);
    float inv = 1.0f / warp_sum(le);

    float acc0 = 0.0f, acc1 = 0.0f;
    int lim = cnt < 32 ? cnt : 32;
    #pragma unroll 4
    for (int idx = 0; idx < lim; idx++) {
        float l = __shfl_sync(0xFFFFFFFFu, v.x, idx);
        int   s = __float_as_int(__shfl_sync(0xFFFFFFFFu, v.y, idx));
        float a = __expf(l - m) * inv;
        float2 xv = *reinterpret_cast<const float2*>(&g_xt[s * DOUT + 2 * lane]);
        acc0 = fmaf(a, xv.x, acc0);
        acc1 = fmaf(a, xv.y, acc1);
    }
    for (int j = beg + 32; j < end; j++) {
        float2 lsv = g_ls[j];
        int   s = __float_as_int(lsv.y);
        float a = __expf(lsv.x - m) * inv;
        float2 xv = *reinterpret_cast<const float2*>(&g_xt[s * DOUT + 2 * lane]);
        acc0 = fmaf(a, xv.x, acc0);
        acc1 = fmaf(a, xv.y, acc1);
    }
    out[n * DOUT + 2 * lane]     = acc0 + b0;
    out[n * DOUT + 2 * lane + 1] = acc1 + b1;
}

// ---------------- launch ----------------
extern "C" void kernel_launch(void* const* d_in, const int* in_sizes, int n_in,
                              void* d_out, int out_size) {
    const float* x         = (const float*)d_in[0];
    const float* edge_attr = (const float*)d_in[1];
    const int*   src       = (const int*)d_in[2];
    const int*   dst       = (const int*)d_in[3];
    const float* W1        = (const float*)d_in[4];
    const float* W2        = (const float*)d_in[5];
    const float* attn      = (const float*)d_in[6];
    const float* bias      = (const float*)d_in[7];
    float* out             = (float*)d_out;

    k_zero_counts<<<(NN + 255) / 256, 256>>>();
    k_hist<<<(EE / 4 + 255) / 256, 256>>>(dst);
    k_node<<<NODE_BLOCKS, 256>>>(x, W1, W2, attn);
    k_scan1<<<SCAN_BLOCKS, SCAN_T>>>();
    k_scan2<<<1, 256>>>();
    k_scan3<<<(NN + 255) / 256, 256>>>();
    k_logits<<<EE / 256, 256>>>(edge_attr, src, dst, W1, attn);
    k_aggregate<<<(NN * 32 + 255) / 256, 256>>>(bias, out);
}

// round 6
// speedup vs baseline: 1.8812x; 1.3720x over previous
#include <cuda_runtime.h>
#include <math.h>

#define NN 100000
#define EE 1280000
#define DIN 64
#define DOUT 64
#define DEDGE 16
#define NEG 0.01f

#define SCAN_T 512
#define SCAN_BLOCKS ((NN + SCAN_T - 1) / SCAN_T)   // 196

#define TM 128                                     // nodes per k_node block
#define NODE_BLOCKS ((NN + TM - 1) / TM)           // 782

typedef unsigned long long ull;

// ---------------- device scratch (static, no allocation) ----------------
__device__ float  g_xt[NN * DOUT];      // x @ W2^T, natural [n][d]
__device__ float  g_sf[NN * DOUT];      // x @ W1a^T, natural [n][d]
__device__ float  g_rdot[NN];
__device__ float2 g_ls[EE];             // CSR-ordered {logit, src-as-bits}
__device__ int    g_count[NN];
__device__ int    g_rowptr[NN + 1];
__device__ int    g_wptr[NN];
__device__ int    g_bsum[SCAN_BLOCKS];

__device__ __forceinline__ float leaky(float v) {
    return fmaxf(v, NEG * v);
}
__device__ __forceinline__ float warp_sum(float v) {
    #pragma unroll
    for (int o = 16; o > 0; o >>= 1) v += __shfl_xor_sync(0xFFFFFFFFu, v, o);
    return v;
}
__device__ __forceinline__ float warp_max(float v) {
    #pragma unroll
    for (int o = 16; o > 0; o >>= 1) v = fmaxf(v, __shfl_xor_sync(0xFFFFFFFFu, v, o));
    return v;
}

// packed f32x2 helpers
__device__ __forceinline__ ull packf2(float lo, float hi) {
    ull r;
    asm("mov.b64 %0, {%1, %2};" : "=l"(r) : "f"(lo), "f"(hi));
    return r;
}
__device__ __forceinline__ void unpackf2(ull v, float& lo, float& hi) {
    asm("mov.b64 {%0, %1}, %2;" : "=f"(lo), "=f"(hi) : "l"(v));
}
__device__ __forceinline__ void ffma2(ull& acc, ull a, ull b) {
    asm("fma.rn.f32x2 %0, %1, %2, %0;" : "+l"(acc) : "l"(a), "l"(b));
}

// ---------------- K0: zero histogram ----------------
__global__ void k_zero_counts() {
    int i = blockIdx.x * blockDim.x + threadIdx.x;
    if (i < NN) g_count[i] = 0;
}

// ---------------- Kh: dst histogram (4 edges/thread) ----------------
__global__ __launch_bounds__(256) void k_hist(const int* __restrict__ dst) {
    int t = blockIdx.x * blockDim.x + threadIdx.x;
    if (t * 4 < EE) {
        int4 d4 = ((const int4*)dst)[t];
        atomicAdd(&g_count[d4.x], 1);
        atomicAdd(&g_count[d4.y], 1);
        atomicAdd(&g_count[d4.z], 1);
        atomicAdd(&g_count[d4.w], 1);
    }
}

// ---------------- K1: node precompute (register-tiled GEMM) ----------------
__global__ __launch_bounds__(256, 2) void k_node(const float* __restrict__ x,
                                                 const float* __restrict__ W1,
                                                 const float* __restrict__ W2,
                                                 const float* __restrict__ attn) {
    __shared__ float xS[TM][65];
    __shared__ float sW[DIN][128];        // [k][d]; d<64: W1a, d>=64: W2
    __shared__ float sAttnR[DIN];

    const int tid = threadIdx.x;
    const int n0  = blockIdx.x * TM;

    for (int idx = tid; idx < DIN * 128; idx += 256) {
        int k = idx >> 7, d = idx & 127;
        sW[k][d] = (d < 64) ? W1[d * (DIN + DEDGE) + k]
                            : W2[(d - 64) * DIN + k];
    }
    if (tid < DIN) sAttnR[tid] = attn[DOUT + tid];

    for (int idx = tid; idx < TM * DIN; idx += 256) {
        int nl = idx >> 6, k = idx & 63;
        int n = n0 + nl;
        if (n >= NN) n = NN - 1;
        xS[nl][k] = x[n * DIN + k];
    }
    __syncthreads();

    const int ty = tid >> 4, tx = tid & 15;
    const int nbase = ty * 8;

    ull acc[8][4];
    #pragma unroll
    for (int j = 0; j < 8; j++)
        #pragma unroll
        for (int p = 0; p < 4; p++) acc[j][p] = 0ULL;

    #pragma unroll 4
    for (int k = 0; k < DIN; k++) {
        ulonglong2 wA = *reinterpret_cast<const ulonglong2*>(&sW[k][tx * 8]);
        ulonglong2 wB = *reinterpret_cast<const ulonglong2*>(&sW[k][tx * 8 + 4]);
        #pragma unroll
        for (int j = 0; j < 8; j++) {
            float xv = xS[nbase + j][k];
            ull xp = packf2(xv, xv);
            ffma2(acc[j][0], wA.x, xp);
            ffma2(acc[j][1], wA.y, xp);
            ffma2(acc[j][2], wB.x, xp);
            ffma2(acc[j][3], wB.y, xp);
        }
    }

    if (tid < TM) {
        int n = n0 + tid;
        if (n < NN) {
            float rd = 0.0f;
            #pragma unroll 8
            for (int k = 0; k < DIN; k++)
                rd += leaky(xS[tid][k]) * sAttnR[k];
            g_rdot[n] = rd;
        }
    }

    #pragma unroll
    for (int j = 0; j < 8; j++) {
        int n = n0 + nbase + j;
        if (n >= NN) continue;
        float* dst = (tx < 8) ? &g_sf[n * DOUT + tx * 8]
                              : &g_xt[n * DOUT + (tx - 8) * 8];
        ulonglong2 v0; v0.x = acc[j][0]; v0.y = acc[j][1];
        ulonglong2 v1; v1.x = acc[j][2]; v1.y = acc[j][3];
        *reinterpret_cast<ulonglong2*>(dst)     = v0;
        *reinterpret_cast<ulonglong2*>(dst + 4) = v1;
    }
}

// ---------------- scan counts -> rowptr ----------------
__global__ __launch_bounds__(SCAN_T) void k_scan1() {
    __shared__ int sh[SCAN_T];
    int i = blockIdx.x * SCAN_T + threadIdx.x;
    int v = (i < NN) ? g_count[i] : 0;
    sh[threadIdx.x] = v;
    __syncthreads();
    #pragma unroll
    for (int off = 1; off < SCAN_T; off <<= 1) {
        int t = (threadIdx.x >= off) ? sh[threadIdx.x - off] : 0;
        __syncthreads();
        sh[threadIdx.x] += t;
        __syncthreads();
    }
    if (i < NN) g_rowptr[i] = sh[threadIdx.x] - v;
    if (threadIdx.x == SCAN_T - 1) g_bsum[blockIdx.x] = sh[SCAN_T - 1];
}

__global__ __launch_bounds__(256) void k_scan2() {
    __shared__ int sh[256];
    int t = threadIdx.x;
    int v = (t < SCAN_BLOCKS) ? g_bsum[t] : 0;
    sh[t] = v;
    __syncthreads();
    #pragma unroll
    for (int off = 1; off < 256; off <<= 1) {
        int tv = (t >= off) ? sh[t - off] : 0;
        __syncthreads();
        sh[t] += tv;
        __syncthreads();
    }
    if (t < SCAN_BLOCKS) g_bsum[t] = sh[t] - v;
}

__global__ void k_scan3() {
    int i = blockIdx.x * blockDim.x + threadIdx.x;
    if (i < NN) {
        int r = g_rowptr[i] + g_bsum[i / SCAN_T];
        g_rowptr[i] = r;
        g_wptr[i]   = r;
    }
    if (i == 0) g_rowptr[NN] = EE;
}

// ---------------- K2: per-edge logits, transpose-reduced, per-lane scatter ----
// Warp handles 32 consecutive edges. Phase A: lane L owns dims (2L,2L+1) and
// writes its partial for edge i to sP[i][L]. Phase B: lane L reduces row L
// (its own edge), adds rdot[dst], and scatters with its own atomic.
__global__ __launch_bounds__(256) void k_logits(const float* __restrict__ edge_attr,
                                                const int* __restrict__ src,
                                                const int* __restrict__ dst,
                                                const float* __restrict__ W1,
                                                const float* __restrict__ attn) {
    __shared__ float2 sW[DEDGE * 32];    // [k][L] = (W1b[2L][k], W1b[2L+1][k])
    __shared__ float  sP[8][32][33];     // [warp][edge][lane], padded

    for (int idx = threadIdx.x; idx < DEDGE * 32; idx += blockDim.x) {
        int k = idx >> 5, L = idx & 31;
        sW[idx] = make_float2(W1[(2 * L) * (DIN + DEDGE) + DIN + k],
                              W1[(2 * L + 1) * (DIN + DEDGE) + DIN + k]);
    }
    __syncthreads();

    const int L = threadIdx.x & 31;
    const int w = threadIdx.x >> 5;

    ull wp[DEDGE];
    #pragma unroll
    for (int k = 0; k < DEDGE; k++) {
        float2 t = sW[k * 32 + L];
        wp[k] = packf2(t.x, t.y);
    }
    const float aL = __ldg(&attn[2 * L]);
    const float aH = __ldg(&attn[2 * L + 1]);

    const int gwarp = blockIdx.x * 8 + w;        // 8 warps x 32 edges = 256 edges/block
    const int base  = gwarp * 32;

    const int s_own = src[base + L];     // coalesced
    const int d_own = dst[base + L];     // coalesced
    const float4* ea4 = (const float4*)edge_attr;

    // Phase A: partials
    #pragma unroll 2
    for (int i = 0; i < 32; i++) {
        const int e = base + i;
        const int s = __shfl_sync(0xFFFFFFFFu, s_own, i);

        float2 sf = *reinterpret_cast<const float2*>(&g_sf[s * DOUT + 2 * L]);
        ull f = packf2(sf.x, sf.y);

        #pragma unroll
        for (int g = 0; g < 4; g++) {
            float4 ev = __ldg(&ea4[e * 4 + g]);           // lane-uniform broadcast
            ffma2(f, wp[4 * g + 0], packf2(ev.x, ev.x));
            ffma2(f, wp[4 * g + 1], packf2(ev.y, ev.y));
            ffma2(f, wp[4 * g + 2], packf2(ev.z, ev.z));
            ffma2(f, wp[4 * g + 3], packf2(ev.w, ev.w));
        }

        float flo, fhi;
        unpackf2(f, flo, fhi);
        sP[w][i][L] = leaky(flo) * aL + leaky(fhi) * aH;
    }
    __syncwarp();

    // Phase B: lane L reduces its own edge (row L), conflict-free via pad 33
    float s0 = 0.f, s1 = 0.f, s2 = 0.f, s3 = 0.f;
    #pragma unroll
    for (int j = 0; j < 32; j += 4) {
        s0 += sP[w][L][j];
        s1 += sP[w][L][j + 1];
        s2 += sP[w][L][j + 2];
        s3 += sP[w][L][j + 3];
    }
    float logit = (s0 + s1) + (s2 + s3) + g_rdot[d_own];

    int pos = atomicAdd(&g_wptr[d_own], 1);               // spread-address
    g_ls[pos] = make_float2(logit, __int_as_float(s_own));
}

// ---------------- K5: warp-per-dst softmax + aggregation ----------------
__global__ __launch_bounds__(256) void k_aggregate(const float* __restrict__ bias,
                                                   float* __restrict__ out) {
    __shared__ float2 sA[8][32];          // [warp][idx] = {alpha, src-bits}

    const int lane = threadIdx.x & 31;
    const int w    = threadIdx.x >> 5;
    const int gw   = (blockIdx.x * blockDim.x + threadIdx.x) >> 5;
    if (gw >= NN) return;
    const int n = gw;

    int beg = g_rowptr[n];
    int end = g_rowptr[n + 1];
    int cnt = end - beg;

    float b0 = bias[2 * lane];
    float b1 = bias[2 * lane + 1];

    if (cnt == 0) {
        out[n * DOUT + 2 * lane]     = b0;
        out[n * DOUT + 2 * lane + 1] = b1;
        return;
    }

    float2 v = make_float2(-INFINITY, 0.0f);
    if (lane < cnt) v = g_ls[beg + lane];

    float lm = v.x;
    for (int j = beg + 32 + lane; j < end; j += 32)
        lm = fmaxf(lm, g_ls[j].x);
    float m = warp_max(lm);

    float le = (lane < cnt) ? __expf(v.x - m) : 0.0f;
    for (int j = beg + 32 + lane; j < end; j += 32)
        le += __expf(g_ls[j].x - m);
    float inv = 1.0f / warp_sum(le);

    // alpha computed once per lane in parallel, staged to smem
    sA[w][lane] = make_float2((lane < cnt) ? __expf(v.x - m) * inv : 0.0f, v.y);
    __syncwarp();

    float acc0 = 0.0f, acc1 = 0.0f;
    int lim = cnt < 32 ? cnt : 32;
    #pragma unroll 4
    for (int idx = 0; idx < lim; idx++) {
        float2 t = sA[w][idx];            // broadcast LDS.64
        int   s = __float_as_int(t.y);
        float a = t.x;
        float2 xv = *reinterpret_cast<const float2*>(&g_xt[s * DOUT + 2 * lane]);
        acc0 = fmaf(a, xv.x, acc0);
        acc1 = fmaf(a, xv.y, acc1);
    }
    for (int j = beg + 32; j < end; j++) {
        float2 lsv = g_ls[j];
        int   s = __float_as_int(lsv.y);
        float a = __expf(lsv.x - m) * inv;
        float2 xv = *reinterpret_cast<const float2*>(&g_xt[s * DOUT + 2 * lane]);
        acc0 = fmaf(a, xv.x, acc0);
        acc1 = fmaf(a, xv.y, acc1);
    }
    out[n * DOUT + 2 * lane]     = acc0 + b0;
    out[n * DOUT + 2 * lane + 1] = acc1 + b1;
}

// ---------------- launch ----------------
extern "C" void kernel_launch(void* const* d_in, const int* in_sizes, int n_in,
                              void* d_out, int out_size) {
    const float* x         = (const float*)d_in[0];
    const float* edge_attr = (const float*)d_in[1];
    const int*   src       = (const int*)d_in[2];
    const int*   dst       = (const int*)d_in[3];
    const float* W1        = (const float*)d_in[4];
    const float* W2        = (const float*)d_in[5];
    const float* attn      = (const float*)d_in[6];
    const float* bias      = (const float*)d_in[7];
    float* out             = (float*)d_out;

    k_zero_counts<<<(NN + 255) / 256, 256>>>();
    k_hist<<<(EE / 4 + 255) / 256, 256>>>(dst);
    k_node<<<NODE_BLOCKS, 256>>>(x, W1, W2, attn);
    k_scan1<<<SCAN_BLOCKS, SCAN_T>>>();
    k_scan2<<<1, 256>>>();
    k_scan3<<<(NN + 255) / 256, 256>>>();
    k_logits<<<EE / 256, 256>>>(edge_attr, src, dst, W1, attn);   // 256 edges/block
    k_aggregate<<<(NN * 32 + 255) / 256, 256>>>(bias, out);
}